// round 2
// baseline (speedup 1.0000x reference)
#include <cuda_runtime.h>
#include <stdint.h>

#define MM    16
#define DIMK  64
#define STR   68            // padded shared row stride (floats): conflict-free + 16B aligned
#define GPB   4             // groups (warps) per block
#define EPSV  0.006f
#define MAXG  8192

__device__ float g_partials[MAXG];

// sqrt on the FMA/ALU pipes only (no MUFU): magic rsqrt + 2 Newton steps, then x*rsqrt(x)
__device__ __forceinline__ float fast_sqrt(float x) {
    float y = __uint_as_float(0x5f3759dfu - (__float_as_uint(x) >> 1));
    float h = 0.5f * x;
    y = y * fmaf(-h * y, y, 1.5f);
    y = y * fmaf(-h * y, y, 1.5f);
    return x * y;
}

// exp(-t) for t in [0, ~0.6]: degree-7 Taylor (Horner), FMA pipe only. abs err < 2e-7.
__device__ __forceinline__ float exp_neg(float t) {
    float u = -t;
    float r = 1.9841270e-4f;            // 1/5040
    r = fmaf(r, u, 1.3888889e-3f);      // 1/720
    r = fmaf(r, u, 8.3333333e-3f);      // 1/120
    r = fmaf(r, u, 4.1666667e-2f);      // 1/24
    r = fmaf(r, u, 1.6666667e-1f);      // 1/6
    r = fmaf(r, u, 0.5f);
    r = fmaf(r, u, 1.0f);
    r = fmaf(r, u, 1.0f);
    return r;
}

__global__ void __launch_bounds__(GPB * 32)
imm_group_kernel(const float* __restrict__ xs,   // ys_t      [B,16,4] -> [G,16,64]
                 const float* __restrict__ ysr,  // ys_r_stop
                 const float* __restrict__ wsc,  // w_scale [B]
                 const float* __restrict__ twg,  // time_weights [B]
                 int G)
{
    __shared__ float shx[GPB][MM * STR];
    __shared__ float shy[GPB][MM * STR];
    __shared__ float shn[GPB][32];     // [0:16) = |x_i|^2, [16:32) = |y_i|^2

    const int warp = threadIdx.x >> 5;
    const int lane = threadIdx.x & 31;
    const int g = blockIdx.x * GPB + warp;
    if (g >= G) return;

    float* X = shx[warp];
    float* Y = shy[warp];

    // ---- stage group tiles (16x64 each) into padded shared ----
    const float4* gx = (const float4*)(xs  + (size_t)g * (MM * DIMK));
    const float4* gy = (const float4*)(ysr + (size_t)g * (MM * DIMK));
#pragma unroll
    for (int t = lane; t < MM * DIMK / 4; t += 32) {
        int row = t >> 4;          // 16 float4 per row
        int c4  = t & 15;
        float4 v = gx[t];
        *(float4*)(X + row * STR + c4 * 4) = v;
        float4 w = gy[t];
        *(float4*)(Y + row * STR + c4 * 4) = w;
    }
    __syncwarp();

    // ---- row norms: lanes 0-15 -> |x_i|^2, lanes 16-31 -> |y_i|^2 ----
    {
        const float* base = (lane < 16 ? X : Y) + (lane & 15) * STR;
        float acc = 0.f;
#pragma unroll
        for (int k = 0; k < DIMK; k += 4) {
            float4 v = *(const float4*)(base + k);
            acc = fmaf(v.x, v.x, acc);
            acc = fmaf(v.y, v.y, acc);
            acc = fmaf(v.z, v.z, acc);
            acc = fmaf(v.w, v.w, acc);
        }
        shn[warp][lane] = acc;
    }
    __syncwarp();

    // ---- three 16x16 Gram matrices; lane owns i in {a, a+8}, j in {b, b+4, b+8, b+12} ----
    const int a = lane >> 2;
    const int b = lane & 3;

    float gxx[2][4] = {{0}}, gyy[2][4] = {{0}}, gxy[2][4] = {{0}};

    const float* xa0p = X + a * STR;
    const float* xa1p = X + (a + 8) * STR;
    const float* ya0p = Y + a * STR;
    const float* ya1p = Y + (a + 8) * STR;

#pragma unroll 4
    for (int kk = 0; kk < DIMK / 4; kk++) {
        const int k = kk * 4;
        float4 xa0 = *(const float4*)(xa0p + k);
        float4 xa1 = *(const float4*)(xa1p + k);
        float4 ya0 = *(const float4*)(ya0p + k);
        float4 ya1 = *(const float4*)(ya1p + k);
#pragma unroll
        for (int c = 0; c < 4; c++) {
            float4 xb = *(const float4*)(X + (b + 4 * c) * STR + k);
            float4 yb = *(const float4*)(Y + (b + 4 * c) * STR + k);

            gxx[0][c] = fmaf(xa0.x, xb.x, gxx[0][c]);
            gxx[0][c] = fmaf(xa0.y, xb.y, gxx[0][c]);
            gxx[0][c] = fmaf(xa0.z, xb.z, gxx[0][c]);
            gxx[0][c] = fmaf(xa0.w, xb.w, gxx[0][c]);
            gxx[1][c] = fmaf(xa1.x, xb.x, gxx[1][c]);
            gxx[1][c] = fmaf(xa1.y, xb.y, gxx[1][c]);
            gxx[1][c] = fmaf(xa1.z, xb.z, gxx[1][c]);
            gxx[1][c] = fmaf(xa1.w, xb.w, gxx[1][c]);

            gyy[0][c] = fmaf(ya0.x, yb.x, gyy[0][c]);
            gyy[0][c] = fmaf(ya0.y, yb.y, gyy[0][c]);
            gyy[0][c] = fmaf(ya0.z, yb.z, gyy[0][c]);
            gyy[0][c] = fmaf(ya0.w, yb.w, gyy[0][c]);
            gyy[1][c] = fmaf(ya1.x, yb.x, gyy[1][c]);
            gyy[1][c] = fmaf(ya1.y, yb.y, gyy[1][c]);
            gyy[1][c] = fmaf(ya1.z, yb.z, gyy[1][c]);
            gyy[1][c] = fmaf(ya1.w, yb.w, gyy[1][c]);

            gxy[0][c] = fmaf(xa0.x, yb.x, gxy[0][c]);
            gxy[0][c] = fmaf(xa0.y, yb.y, gxy[0][c]);
            gxy[0][c] = fmaf(xa0.z, yb.z, gxy[0][c]);
            gxy[0][c] = fmaf(xa0.w, yb.w, gxy[0][c]);
            gxy[1][c] = fmaf(xa1.x, yb.x, gxy[1][c]);
            gxy[1][c] = fmaf(xa1.y, yb.y, gxy[1][c]);
            gxy[1][c] = fmaf(xa1.z, yb.z, gxy[1][c]);
            gxy[1][c] = fmaf(xa1.w, yb.w, gxy[1][c]);
        }
    }

    // ---- epilogue: d^2 = n_i + n_j - 2 g_ij, clamp at EPS^2, sqrt, poly-exp ----
    const float* nrm = shn[warp];
    const float nxa[2] = { nrm[a],      nrm[a + 8] };
    const float nya[2] = { nrm[16 + a], nrm[16 + a + 8] };
    const float wsa[2] = { wsc[g * MM + a] * (1.0f / (float)DIMK),
                           wsc[g * MM + a + 8] * (1.0f / (float)DIMK) };

    float lsum = 0.f;
#pragma unroll
    for (int p = 0; p < 2; p++) {
        const float w64 = wsa[p];
#pragma unroll
        for (int c = 0; c < 4; c++) {
            const int j = b + 4 * c;
            const float nxj = nrm[j];
            const float nyj = nrm[16 + j];

            float d2xx = fmaxf(fmaf(-2.f, gxx[p][c], nxa[p] + nxj), EPSV * EPSV);
            float d2yy = fmaxf(fmaf(-2.f, gyy[p][c], nya[p] + nyj), EPSV * EPSV);
            float d2xy = fmaxf(fmaf(-2.f, gxy[p][c], nxa[p] + nyj), EPSV * EPSV);

            float txx = exp_neg(w64 * fast_sqrt(d2xx));
            float tyy = exp_neg(w64 * fast_sqrt(d2yy));
            float txy = exp_neg(w64 * fast_sqrt(d2xy));
            lsum += txx + tyy - 2.f * txy;
        }
    }

    // warp reduction -> per-group partial (deterministic, no atomics)
#pragma unroll
    for (int off = 16; off; off >>= 1)
        lsum += __shfl_xor_sync(0xffffffffu, lsum, off);

    if (lane == 0)
        g_partials[g] = lsum * twg[g * MM] * (1.0f / (float)(MM * MM));
}

__global__ void imm_reduce_kernel(float* __restrict__ out, int G)
{
    __shared__ float s[256];
    float acc = 0.f;
    for (int i = threadIdx.x; i < G; i += 256)
        acc += g_partials[i];
    s[threadIdx.x] = acc;
    __syncthreads();
#pragma unroll
    for (int off = 128; off; off >>= 1) {
        if (threadIdx.x < off) s[threadIdx.x] += s[threadIdx.x + off];
        __syncthreads();
    }
    if (threadIdx.x == 0)
        out[0] = s[0] / (float)G;
}

extern "C" void kernel_launch(void* const* d_in, const int* in_sizes, int n_in,
                              void* d_out, int out_size)
{
    const float* xs  = (const float*)d_in[0];   // ys_t
    const float* ysr = (const float*)d_in[1];   // ys_r_stop
    const float* ws  = (const float*)d_in[2];   // w_scale
    const float* tw  = (const float*)d_in[3];   // time_weights

    const int n = in_sizes[0];          // B * 16 * 4
    const int B = n / DIMK;             // pred*obs = 64 elems per batch row
    int G = B / MM;
    if (G > MAXG) G = MAXG;

    const int blocks = (G + GPB - 1) / GPB;
    imm_group_kernel<<<blocks, GPB * 32>>>(xs, ysr, ws, tw, G);
    imm_reduce_kernel<<<1, 256>>>((float*)d_out, G);
}

// round 3
// speedup vs baseline: 1.4429x; 1.4429x over previous
#include <cuda_runtime.h>
#include <stdint.h>

#define MM    16
#define DIMK  64
#define STR   68            // padded shared row stride (floats)
#define GPB   4             // groups (warps) per block
#define EPSV  0.006f
#define MAXG  8192
#define MAXBLK (MAXG / GPB)

__device__ float        g_blocksum[MAXBLK];
__device__ unsigned int g_count = 0;

union F4 {
    float4 v;
    unsigned long long u[2];
    float f[4];
};

// packed dual-FMA (Blackwell FFMA2): (a.lo*b.lo+c.lo, a.hi*b.hi+c.hi)
__device__ __forceinline__ unsigned long long ffma2(unsigned long long a,
                                                    unsigned long long b,
                                                    unsigned long long c) {
    unsigned long long d;
    asm("fma.rn.f32x2 %0, %1, %2, %3;" : "=l"(d) : "l"(a), "l"(b), "l"(c));
    return d;
}

__device__ __forceinline__ float hsum2(unsigned long long u) {
    float lo, hi;
    asm("mov.b64 {%0, %1}, %2;" : "=f"(lo), "=f"(hi) : "l"(u));
    return lo + hi;
}

// sqrt on FMA/ALU pipes only (no MUFU): magic rsqrt + 2 Newton steps, then x*rsqrt(x)
__device__ __forceinline__ float fast_sqrt(float x) {
    float y = __uint_as_float(0x5f3759dfu - (__float_as_uint(x) >> 1));
    float h = 0.5f * x;
    y = y * fmaf(-h * y, y, 1.5f);
    y = y * fmaf(-h * y, y, 1.5f);
    return x * y;
}

// exp(-t) for t in [0, ~0.6]: degree-7 Taylor (Horner), FMA pipe only. abs err < 2e-7.
__device__ __forceinline__ float exp_neg(float t) {
    float u = -t;
    float r = 1.9841270e-4f;
    r = fmaf(r, u, 1.3888889e-3f);
    r = fmaf(r, u, 8.3333333e-3f);
    r = fmaf(r, u, 4.1666667e-2f);
    r = fmaf(r, u, 1.6666667e-1f);
    r = fmaf(r, u, 0.5f);
    r = fmaf(r, u, 1.0f);
    r = fmaf(r, u, 1.0f);
    return r;
}

__global__ void __launch_bounds__(GPB * 32)
imm_fused_kernel(const float* __restrict__ xs,   // ys_t      [G,16,64]
                 const float* __restrict__ ysr,  // ys_r_stop [G,16,64]
                 const float* __restrict__ wsc,  // w_scale [B]
                 const float* __restrict__ twg,  // time_weights [B]
                 float* __restrict__ out,
                 int G)
{
    __shared__ float shx[GPB][MM * STR];
    __shared__ float shy[GPB][MM * STR];
    __shared__ float shn[GPB][32];      // [0:16)=|x_i|^2, [16:32)=|y_i|^2
    __shared__ float s_part[GPB];
    __shared__ int   s_last;

    const int warp = threadIdx.x >> 5;
    const int lane = threadIdx.x & 31;
    const int g = blockIdx.x * GPB + warp;
    const bool valid = (g < G);

    float* X = shx[warp];
    float* Y = shy[warp];

    // ---- stage group tiles (16x64 each) into padded shared ----
    if (valid) {
        const float4* gx = (const float4*)(xs  + (size_t)g * (MM * DIMK));
        const float4* gy = (const float4*)(ysr + (size_t)g * (MM * DIMK));
#pragma unroll
        for (int t = lane; t < MM * DIMK / 4; t += 32) {
            int row = t >> 4;
            int c4  = t & 15;
            float4 v = gx[t];
            *(float4*)(X + row * STR + c4 * 4) = v;
            float4 w = gy[t];
            *(float4*)(Y + row * STR + c4 * 4) = w;
        }
    }
    __syncwarp();

    float lsum = 0.f;

    if (valid) {
        // ---- row norms: lanes 0-15 -> |x_i|^2, lanes 16-31 -> |y_i|^2 ----
        {
            const float* base = (lane < 16 ? X : Y) + (lane & 15) * STR;
            float acc = 0.f;
#pragma unroll
            for (int k = 0; k < DIMK; k += 4) {
                float4 v = *(const float4*)(base + k);
                acc = fmaf(v.x, v.x, acc);
                acc = fmaf(v.y, v.y, acc);
                acc = fmaf(v.z, v.z, acc);
                acc = fmaf(v.w, v.w, acc);
            }
            shn[warp][lane] = acc;
        }
        __syncwarp();

        // ---- three 16x16 Gram matrices via packed f32x2 FMA ----
        // lane owns i in {a, a+8}, j in {b, b+4, b+8, b+12}
        const int a = lane >> 2;
        const int b = lane & 3;

        unsigned long long Gxx[2][4], Gyy[2][4], Gxy[2][4];
#pragma unroll
        for (int p = 0; p < 2; p++)
#pragma unroll
            for (int c = 0; c < 4; c++) {
                Gxx[p][c] = 0ull; Gyy[p][c] = 0ull; Gxy[p][c] = 0ull;
            }

        const float* xa0p = X + a * STR;
        const float* xa1p = X + (a + 8) * STR;
        const float* ya0p = Y + a * STR;
        const float* ya1p = Y + (a + 8) * STR;

#pragma unroll 4
        for (int kk = 0; kk < DIMK / 4; kk++) {
            const int k = kk * 4;
            F4 xa0, xa1, ya0, ya1;
            xa0.v = *(const float4*)(xa0p + k);
            xa1.v = *(const float4*)(xa1p + k);
            ya0.v = *(const float4*)(ya0p + k);
            ya1.v = *(const float4*)(ya1p + k);
#pragma unroll
            for (int c = 0; c < 4; c++) {
                F4 xb, yb;
                xb.v = *(const float4*)(X + (b + 4 * c) * STR + k);
                yb.v = *(const float4*)(Y + (b + 4 * c) * STR + k);

                Gxx[0][c] = ffma2(xa0.u[0], xb.u[0], Gxx[0][c]);
                Gxx[0][c] = ffma2(xa0.u[1], xb.u[1], Gxx[0][c]);
                Gxx[1][c] = ffma2(xa1.u[0], xb.u[0], Gxx[1][c]);
                Gxx[1][c] = ffma2(xa1.u[1], xb.u[1], Gxx[1][c]);

                Gyy[0][c] = ffma2(ya0.u[0], yb.u[0], Gyy[0][c]);
                Gyy[0][c] = ffma2(ya0.u[1], yb.u[1], Gyy[0][c]);
                Gyy[1][c] = ffma2(ya1.u[0], yb.u[0], Gyy[1][c]);
                Gyy[1][c] = ffma2(ya1.u[1], yb.u[1], Gyy[1][c]);

                Gxy[0][c] = ffma2(xa0.u[0], yb.u[0], Gxy[0][c]);
                Gxy[0][c] = ffma2(xa0.u[1], yb.u[1], Gxy[0][c]);
                Gxy[1][c] = ffma2(xa1.u[0], yb.u[0], Gxy[1][c]);
                Gxy[1][c] = ffma2(xa1.u[1], yb.u[1], Gxy[1][c]);
            }
        }

        // ---- epilogue: d^2 = n_i + n_j - 2 g_ij, clamp, sqrt, poly-exp ----
        const float* nrm = shn[warp];
        const float nxa[2] = { nrm[a],      nrm[a + 8] };
        const float nya[2] = { nrm[16 + a], nrm[16 + a + 8] };
        const float wsa[2] = { wsc[g * MM + a]     * (1.0f / (float)DIMK),
                               wsc[g * MM + a + 8] * (1.0f / (float)DIMK) };

#pragma unroll
        for (int p = 0; p < 2; p++) {
            const float w64 = wsa[p];
#pragma unroll
            for (int c = 0; c < 4; c++) {
                const int j = b + 4 * c;
                const float nxj = nrm[j];
                const float nyj = nrm[16 + j];

                float gxx = hsum2(Gxx[p][c]);
                float gyy = hsum2(Gyy[p][c]);
                float gxy = hsum2(Gxy[p][c]);

                float d2xx = fmaxf(fmaf(-2.f, gxx, nxa[p] + nxj), EPSV * EPSV);
                float d2yy = fmaxf(fmaf(-2.f, gyy, nya[p] + nyj), EPSV * EPSV);
                float d2xy = fmaxf(fmaf(-2.f, gxy, nxa[p] + nyj), EPSV * EPSV);

                float txx = exp_neg(w64 * fast_sqrt(d2xx));
                float tyy = exp_neg(w64 * fast_sqrt(d2yy));
                float txy = exp_neg(w64 * fast_sqrt(d2xy));
                lsum += txx + tyy - 2.f * txy;
            }
        }

        // warp reduction -> per-group value (deterministic)
#pragma unroll
        for (int off = 16; off; off >>= 1)
            lsum += __shfl_xor_sync(0xffffffffu, lsum, off);
    }

    if (lane == 0)
        s_part[warp] = valid ? lsum * twg[g * MM] * (1.0f / (float)(MM * MM)) : 0.f;
    __syncthreads();

    // ---- block partial + last-block-done grid reduction ----
    if (threadIdx.x == 0) {
        float bs = 0.f;
#pragma unroll
        for (int w = 0; w < GPB; w++) bs += s_part[w];
        g_blocksum[blockIdx.x] = bs;
        __threadfence();
        unsigned int v = atomicAdd(&g_count, 1u);
        s_last = (v == gridDim.x - 1u) ? 1 : 0;
    }
    __syncthreads();

    if (s_last) {
        const int nb = gridDim.x;
        float acc = 0.f;
        for (int i = threadIdx.x; i < nb; i += GPB * 32)
            acc += g_blocksum[i];
#pragma unroll
        for (int off = 16; off; off >>= 1)
            acc += __shfl_xor_sync(0xffffffffu, acc, off);
        if (lane == 0) s_part[warp] = acc;
        __syncthreads();
        if (threadIdx.x == 0) {
            float tot = 0.f;
#pragma unroll
            for (int w = 0; w < GPB; w++) tot += s_part[w];
            out[0] = tot / (float)G;
            g_count = 0;   // reset for next graph replay
        }
    }
}

extern "C" void kernel_launch(void* const* d_in, const int* in_sizes, int n_in,
                              void* d_out, int out_size)
{
    const float* xs  = (const float*)d_in[0];   // ys_t
    const float* ysr = (const float*)d_in[1];   // ys_r_stop
    const float* ws  = (const float*)d_in[2];   // w_scale
    const float* tw  = (const float*)d_in[3];   // time_weights

    const int n = in_sizes[0];          // B * 16 * 4
    const int B = n / DIMK;
    int G = B / MM;
    if (G > MAXG) G = MAXG;

    const int blocks = (G + GPB - 1) / GPB;
    imm_fused_kernel<<<blocks, GPB * 32>>>(xs, ysr, ws, tw, (float*)d_out, G);
}